// round 14
// baseline (speedup 1.0000x reference)
#include <cuda_runtime.h>
#include <cstdint>

#define B 512
#define T 2048
#define K 32
#define CH 64             // time steps per staged chunk
#define NCH (T / CH)      // 32 chunks
#define WPC 4             // warps (batches) per CTA -> 1/SMSP, grid=128
#define CHB (CH * K * 4)  // pot chunk bytes = 8192
#define BPCH (CH * K)     // bp chunk bytes = 2048
#define FULL 0xffffffffu

// dynamic smem (bytes): pot[WPC][2][CH*K] f32 | bp[WPC][2][CH*K] u8 | st[WPC][K] f32
#define POT_BYTES (WPC * 2 * CH * K * 4)
#define BP_BYTES  (WPC * 2 * CH * K)
#define SMEM_DYN_BYTES (POT_BYTES + BP_BYTES + WPC * K * 4)

// backpointer trace: g_bp[b][t][j] = argmax_i(s_i(t-1)+T[i][j]), t=1..T-1
__device__ unsigned char g_bp[(size_t)B * T * K];

#define WSYNC() __syncwarp()

__device__ __forceinline__ void cp16(uint32_t saddr, const void* gptr) {
    asm volatile("cp.async.cg.shared.global [%0], [%1], 16;" :: "r"(saddr), "l"(gptr));
}
#define CP_COMMIT()  asm volatile("cp.async.commit_group;")
#define CP_WAIT(n)   asm volatile("cp.async.wait_group %0;" :: "n"(n))

__device__ __forceinline__ void bulk_s2g(void* gdst, uint32_t ssrc, uint32_t bytes) {
    asm volatile("cp.async.bulk.global.shared::cta.bulk_group [%0], [%1], %2;"
                 :: "l"(gdst), "r"(ssrc), "r"(bytes) : "memory");
}
#define BULK_COMMIT()    asm volatile("cp.async.bulk.commit_group;")
#define BULK_WAIT_RD(n)  asm volatile("cp.async.bulk.wait_group.read %0;" :: "n"(n))
#define BULK_WAIT(n)     asm volatile("cp.async.bulk.wait_group %0;" :: "n"(n))
#define FENCE_ASYNC()    asm volatile("fence.proxy.async.shared::cta;" ::: "memory")

__global__ void __launch_bounds__(WPC * 32, 1) crf_viterbi_kernel(
    const float* __restrict__ pot,     // [B, T, K]
    const float* __restrict__ trans,   // [K, K]
    float* __restrict__ out)           // [B, T, K] one-hot
{
    extern __shared__ __align__(16) unsigned char dynb[];
    float* potBase          = (float*)dynb;                       // POT_BYTES
    unsigned char* bpBase   = dynb + POT_BYTES;                   // BP_BYTES
    float* stBase           = (float*)(dynb + POT_BYTES + BP_BYTES);

    const int lane = threadIdx.x & 31;
    const int w    = threadIdx.x >> 5;
    const int b    = blockIdx.x * WPC + w;

    const char* pB  = (const char*)(pot + (size_t)b * T * K);
    char* bpG       = (char*)(g_bp + (size_t)b * T * K);
    float* ob       = out + (size_t)b * T * K + lane;

    float* potW0 = potBase + (w * 2 + 0) * CH * K;
    float* potW1 = potBase + (w * 2 + 1) * CH * K;
    unsigned char* bpW0 = bpBase + (w * 2 + 0) * CH * K;
    unsigned char* bpW1 = bpBase + (w * 2 + 1) * CH * K;
    float* stW   = stBase + w * K;
    const uint32_t potA0 = (uint32_t)__cvta_generic_to_shared(potW0);
    const uint32_t potA1 = (uint32_t)__cvta_generic_to_shared(potW1);
    const uint32_t bpA0  = (uint32_t)__cvta_generic_to_shared(bpW0);
    const uint32_t bpA1  = (uint32_t)__cvta_generic_to_shared(bpW1);

    // transition column `lane`: tj[i] = trans[i][lane]
    float tj[K];
#pragma unroll
    for (int i = 0; i < K; i++) tj[i] = __ldg(trans + i * K + lane);

    // zero the never-written bp row 0 of chunk 0 (flushed but unused)
    bpW0[lane] = 0;

    // ---- stage forward pot chunks 0 and 1 ----
#pragma unroll
    for (int i = 0; i < 16; i++)
        cp16(potA0 + lane * 16 + i * 512, pB + lane * 16 + i * 512);
    CP_COMMIT();
#pragma unroll
    for (int i = 0; i < 16; i++)
        cp16(potA1 + lane * 16 + i * 512, pB + CHB + lane * 16 + i * 512);
    CP_COMMIT();
    CP_WAIT(1);
    WSYNC();

    float s = potW0[lane];            // s(0) = pot(0)

// forward step: values + bp mask. Chain = STS -> 8xLDS.128 -> adds -> max tree -> s.
// Mask/ffs/bp-store feed nothing on the chain -> scheduled into stall shadow.
#define FSTEP(r, pc, bprow) do {                                          \
        const float pcur = (pc)[(r) * K + lane];                          \
        stW[lane] = s;                                                    \
        const float4* sp = (const float4*)stW;                           \
        float v[32];                                                      \
        _Pragma("unroll")                                                 \
        for (int q = 0; q < 8; q++) {                                     \
            float4 qq = sp[q];                                            \
            v[4*q+0] = qq.x + tj[4*q+0];                                  \
            v[4*q+1] = qq.y + tj[4*q+1];                                  \
            v[4*q+2] = qq.z + tj[4*q+2];                                  \
            v[4*q+3] = qq.w + tj[4*q+3];                                  \
        }                                                                 \
        float m = fmaxf(fmaxf(v[0], v[1]), fmaxf(v[2], v[3]));            \
        _Pragma("unroll")                                                 \
        for (int q = 1; q < 8; q++) {                                     \
            float qm = fmaxf(fmaxf(v[4*q+0], v[4*q+1]),                   \
                             fmaxf(v[4*q+2], v[4*q+3]));                  \
            m = fmaxf(m, qm);                                             \
        }                                                                 \
        unsigned msk = 0;                                                 \
        _Pragma("unroll")                                                 \
        for (int i = 0; i < 32; i++)                                      \
            if (v[i] == m) msk |= (1u << i);                              \
        (bprow)[(r) * K + lane] = (unsigned char)(__ffs(msk) - 1);        \
        s = m + pcur;                                                     \
    } while (0)

    // ================= forward =================
    // chunk 0 (rows 1..CH-1), peeled
    {
#pragma unroll 8
        for (int r = 1; r < CH; r++) FSTEP(r, potW0, bpW0);
        WSYNC();
        FENCE_ASYNC();
        if (lane == 0) {
            bulk_s2g((void*)bpG, bpA0, BPCH);
            BULK_COMMIT();
            BULK_WAIT_RD(1);
        }
        const char* src = pB + 2 * (size_t)CHB;
#pragma unroll
        for (int i = 0; i < 16; i++)
            cp16(potA0 + lane * 16 + i * 512, src + lane * 16 + i * 512);
        CP_COMMIT();
        CP_WAIT(1);
        WSYNC();
    }
    for (int c = 1; c < NCH; c++) {
        const float* pc      = (c & 1) ? potW1 : potW0;
        unsigned char* bprow = (c & 1) ? bpW1 : bpW0;
#pragma unroll 8
        for (int r = 0; r < CH; r++) FSTEP(r, pc, bprow);
        WSYNC();
        if (c <= NCH - 3) {                       // last 2 bp chunks stay resident
            FENCE_ASYNC();
            if (lane == 0) {
                bulk_s2g((void*)(bpG + (size_t)c * BPCH), (c & 1) ? bpA1 : bpA0, BPCH);
                BULK_COMMIT();
                BULK_WAIT_RD(1);
            }
        }
        if (c + 2 < NCH) {
            const uint32_t dst = ((c & 1) == 0) ? potA0 : potA1;
            const char* src = pB + (size_t)(c + 2) * CHB;
#pragma unroll
            for (int i = 0; i < 16; i++)
                cp16(dst + lane * 16 + i * 512, src + lane * 16 + i * 512);
            CP_COMMIT();
            CP_WAIT(1);
            WSYNC();
        } else if (c + 1 < NCH) {
            CP_WAIT(0);
            WSYNC();
        }
    }

    // ---- final tag: first-index argmax over lanes of s(T-1) ----
    float mm = s;
#pragma unroll
    for (int off = 16; off; off >>= 1) mm = fmaxf(mm, __shfl_xor_sync(FULL, mm, off));
    int tag = __ffs(__ballot_sync(FULL, s == mm)) - 1;
    ob[(size_t)(T - 1) * K] = (lane == tag) ? 1.0f : 0.0f;

    // bp bulk stores must be globally visible before cp.async re-reads
    if (lane == 0) BULK_WAIT(0);
    WSYNC();

    // ================= backtrack: pure bp pointer chase =================
    // chunks NCH-1 (buf1) and NCH-2 (buf0) still resident.

// one chase step at time t (row r of chunk buffer bpc): tag(t-1) = bp_t[tag(t)]
#define CSTEP(t, r, bpc) do {                                             \
        tag = (int)(bpc)[(r) * K + tag];                                  \
        ob[(size_t)((t) - 1) * K] = (lane == tag) ? 1.0f : 0.0f;          \
    } while (0)

// stage bp chunk (c-2) into parity buffer of (c), ensure chunk (c-1) ready
#define STAGE_BP(c) do {                                                  \
        const uint32_t bd = (((c) & 1) == 0) ? bpA0 : bpA1;               \
        const char* gb = bpG + (size_t)((c) - 2) * BPCH;                  \
        _Pragma("unroll")                                                 \
        for (int i = 0; i < 4; i++) cp16(bd + lane*16 + i*512, gb + lane*16 + i*512); \
        CP_COMMIT();                                                      \
        CP_WAIT(1);                                                       \
        WSYNC();                                                          \
    } while (0)

    // chunk NCH-1: t = T-1 .. (NCH-1)*CH  (rows CH-1..0)
    {
#pragma unroll 16
        for (int r = CH - 1; r >= 0; r--) CSTEP((NCH - 1) * CH + r, r, bpW1);
        STAGE_BP(NCH - 1);
    }
    for (int c = NCH - 2; c >= 1; c--) {
        const unsigned char* bpc = (c & 1) ? bpW1 : bpW0;
#pragma unroll 16
        for (int r = CH - 1; r >= 0; r--) CSTEP(c * CH + r, r, bpc);
        if (c >= 2) {
            STAGE_BP(c);
        } else {
            CP_WAIT(0);
            WSYNC();
        }
    }
    // chunk 0: t = CH-1 .. 1 (row 0 is t=0, no bp)
    {
#pragma unroll 16
        for (int r = CH - 1; r >= 1; r--) CSTEP(r, r, bpW0);
    }
}

extern "C" void kernel_launch(void* const* d_in, const int* in_sizes, int n_in,
                              void* d_out, int out_size)
{
    const float* pot   = (const float*)d_in[0];
    const float* trans = (const float*)d_in[1];
    float* outp        = (float*)d_out;
    cudaFuncSetAttribute(crf_viterbi_kernel,
                         cudaFuncAttributeMaxDynamicSharedMemorySize, SMEM_DYN_BYTES);
    crf_viterbi_kernel<<<B / WPC, WPC * 32, SMEM_DYN_BYTES>>>(pot, trans, outp);
}

// round 15
// speedup vs baseline: 1.5633x; 1.5633x over previous
#include <cuda_runtime.h>
#include <cstdint>

#define B 512
#define T 2048
#define K 32
#define CH 64            // time steps per staged chunk
#define NCH (T / CH)     // 32 chunks
#define WPC 4            // warps (batches) per CTA -> 1 per SMSP, grid=128
#define CHB (CH * K * 4) // 8192
#define FULL 0xffffffffu

#define POT_F (WPC * 2 * CH * K)
#define M_F   (WPC * 2 * CH * K)
#define SMEM_DYN_BYTES ((POT_F + M_F + K * K + WPC * K) * 4)

// m-trace; last 2 chunks per batch never hit gmem
__device__ float g_m[(size_t)B * T * K];

#define ADD2(out, a, b) asm("add.rn.f32x2 %0, %1, %2;" : "=l"(out) : "l"(a), "l"(b))
#define UNPK(lo, hi, v) asm("mov.b64 {%0, %1}, %2;" : "=f"(lo), "=f"(hi) : "l"(v))
#define WSYNC()         __syncwarp()

__device__ __forceinline__ void cp16(uint32_t saddr, const void* gptr) {
    asm volatile("cp.async.cg.shared.global [%0], [%1], 16;" :: "r"(saddr), "l"(gptr));
}
#define CP_COMMIT()  asm volatile("cp.async.commit_group;")
#define CP_WAIT(n)   asm volatile("cp.async.wait_group %0;" :: "n"(n))

__device__ __forceinline__ void bulk_s2g(void* gdst, uint32_t ssrc, uint32_t bytes) {
    asm volatile("cp.async.bulk.global.shared::cta.bulk_group [%0], [%1], %2;"
                 :: "l"(gdst), "r"(ssrc), "r"(bytes) : "memory");
}
#define BULK_COMMIT()    asm volatile("cp.async.bulk.commit_group;")
#define BULK_WAIT_RD(n)  asm volatile("cp.async.bulk.wait_group.read %0;" :: "n"(n))
#define BULK_WAIT(n)     asm volatile("cp.async.bulk.wait_group %0;" :: "n"(n))
#define FENCE_ASYNC()    asm volatile("fence.proxy.async.shared::cta;" ::: "memory")

__global__ void __launch_bounds__(WPC * 32, 1) crf_viterbi_kernel(
    const float* __restrict__ pot,     // [B, T, K]
    const float* __restrict__ trans,   // [K, K]
    float* __restrict__ out)           // [B, T, K] one-hot
{
    extern __shared__ __align__(16) float dyn[];
    float* potBase = dyn;
    float* mBase   = dyn + POT_F;
    float* trColS  = mBase + M_F;              // trColS[j*K+i] = trans[i][j]
    float* stBase  = trColS + K * K;

    const int lane = threadIdx.x & 31;
    const int w    = threadIdx.x >> 5;
    const int b    = blockIdx.x * WPC + w;

    const char* pB = (const char*)(pot + (size_t)b * T * K);
    const char* mB = (const char*)(g_m + (size_t)b * T * K);
    float* ob      = out + (size_t)b * T * K + lane;

    float* potW0 = potBase + (w * 2 + 0) * CH * K;
    float* potW1 = potBase + (w * 2 + 1) * CH * K;
    float* mW0   = mBase + (w * 2 + 0) * CH * K;
    float* mW1   = mBase + (w * 2 + 1) * CH * K;
    float* stW   = stBase + w * K;
    const uint32_t potA0 = (uint32_t)__cvta_generic_to_shared(potW0);
    const uint32_t potA1 = (uint32_t)__cvta_generic_to_shared(potW1);
    const uint32_t mA0   = (uint32_t)__cvta_generic_to_shared(mW0);
    const uint32_t mA1   = (uint32_t)__cvta_generic_to_shared(mW1);

    // packed transition column `lane`: tj2[q] = (trans[2q][lane], trans[2q+1][lane])
    unsigned long long tj2[16];
#pragma unroll
    for (int q = 0; q < 16; q++) {
        float lo = __ldg(trans + (2 * q) * K + lane);
        float hi = __ldg(trans + (2 * q + 1) * K + lane);
        asm("mov.b64 %0, {%1, %2};" : "=l"(tj2[q]) : "f"(lo), "f"(hi));
    }
    if (w == 0) {
#pragma unroll
        for (int i = 0; i < K; i++) trColS[lane * K + i] = trans[i * K + lane];
    }
    __syncthreads();

    // ---- stage forward chunks 0 and 1 ----
#pragma unroll
    for (int i = 0; i < 16; i++)
        cp16(potA0 + lane * 16 + i * 512, pB + lane * 16 + i * 512);
    CP_COMMIT();
#pragma unroll
    for (int i = 0; i < 16; i++)
        cp16(potA1 + lane * 16 + i * 512, pB + CHB + lane * 16 + i * 512);
    CP_COMMIT();
    CP_WAIT(1);
    WSYNC();

    float s = potW0[lane];            // s(0) = pot(0)
    const float pot0 = s;
    float mlast = 0.0f;

// R9 packed forward step (values only; same-warp STS->LDS in program order)
#define FSTEP(r, pc, mrow) do {                                           \
        const float pcur = (pc)[(r) * K + lane];                          \
        stW[lane] = s;                                                    \
        const ulonglong2* sp = (const ulonglong2*)stW;                    \
        unsigned long long v2[16];                                        \
        _Pragma("unroll")                                                 \
        for (int q = 0; q < 8; q++) {                                     \
            ulonglong2 rr = sp[q];                                        \
            ADD2(v2[2 * q],     rr.x, tj2[2 * q]);                        \
            ADD2(v2[2 * q + 1], rr.y, tj2[2 * q + 1]);                    \
        }                                                                 \
        float m0[16];                                                     \
        _Pragma("unroll")                                                 \
        for (int q = 0; q < 16; q++) {                                    \
            float lo, hi; UNPK(lo, hi, v2[q]);                            \
            m0[q] = fmaxf(lo, hi);                                        \
        }                                                                 \
        float m1[8];                                                      \
        _Pragma("unroll")                                                 \
        for (int q = 0; q < 8; q++) m1[q] = fmaxf(m0[2*q], m0[2*q+1]);    \
        float m2[4];                                                      \
        _Pragma("unroll")                                                 \
        for (int q = 0; q < 4; q++) m2[q] = fmaxf(m1[2*q], m1[2*q+1]);    \
        const float m = fmaxf(fmaxf(m2[0], m2[1]), fmaxf(m2[2], m2[3]));  \
        (mrow)[(r) * K + lane] = m;                                       \
        s = m + pcur;                                                     \
        mlast = m;                                                        \
    } while (0)

    // ================= forward =================
    {
#pragma unroll 16
        for (int r = 1; r < CH; r++) FSTEP(r, potW0, mW0);
        WSYNC();
        FENCE_ASYNC();
        if (lane == 0) {
            bulk_s2g((void*)mB, mA0, CHB);
            BULK_COMMIT();
            BULK_WAIT_RD(1);
        }
        const char* src = pB + 2 * (size_t)CHB;
#pragma unroll
        for (int i = 0; i < 16; i++)
            cp16(potA0 + lane * 16 + i * 512, src + lane * 16 + i * 512);
        CP_COMMIT();
        CP_WAIT(1);
        WSYNC();
    }
    for (int c = 1; c < NCH; c++) {
        const float* pc = (c & 1) ? potW1 : potW0;
        float* mrow     = (c & 1) ? mW1 : mW0;
#pragma unroll 16
        for (int r = 0; r < CH; r++) FSTEP(r, pc, mrow);
        WSYNC();
        if (c <= NCH - 3) {
            FENCE_ASYNC();
            if (lane == 0) {
                bulk_s2g((void*)(mB + (size_t)c * CHB), (c & 1) ? mA1 : mA0, CHB);
                BULK_COMMIT();
                BULK_WAIT_RD(1);
            }
        }
        if (c + 2 < NCH) {
            const uint32_t dst = ((c & 1) == 0) ? potA0 : potA1;
            const char* src = pB + (size_t)(c + 2) * CHB;
#pragma unroll
            for (int i = 0; i < 16; i++)
                cp16(dst + lane * 16 + i * 512, src + lane * 16 + i * 512);
            CP_COMMIT();
            CP_WAIT(1);
            WSYNC();
        } else if (c + 1 < NCH) {
            CP_WAIT(0);
            WSYNC();
        }
    }

    // ---- final tag ----
    float mm = s;
#pragma unroll
    for (int off = 16; off; off >>= 1) mm = fmaxf(mm, __shfl_xor_sync(FULL, mm, off));
    int tag = __ffs(__ballot_sync(FULL, s == mm)) - 1;
    ob[(size_t)(T - 1) * K] = (lane == tag) ? 1.0f : 0.0f;

    if (lane == 0) BULK_WAIT(0);
    WSYNC();

    // ================= backtrack (chunks NCH-1, NCH-2 resident) =================
    float mcur = mlast;

// backtrack step: tag-independent loads + sprev hoisted ahead of the tag chain
#define BSTEP(tp, r, mc, pcS) do {                                        \
        const float mprev = (mc)[(r) * K + lane];                         \
        const float pprev = (pcS)[(r) * K + lane];                        \
        const float sprev = mprev + pprev;                                \
        const float target = __shfl_sync(FULL, mcur, tag);                \
        const float tv = trColS[tag * K + lane];                          \
        const unsigned msk = __ballot_sync(FULL, sprev + tv == target);   \
        tag = __ffs(msk) - 1;                                             \
        mcur = mprev;                                                     \
        ob[(size_t)(tp) * K] = (lane == tag) ? 1.0f : 0.0f;               \
    } while (0)

#define STAGE_BT(c) do {                                                  \
        const uint32_t md = (((c) & 1) == 0) ? mA0 : mA1;                 \
        const uint32_t pd = (((c) & 1) == 0) ? potA0 : potA1;             \
        const char* gm = mB + (size_t)((c) - 2) * CHB;                    \
        const char* gp = pB + (size_t)((c) - 2) * CHB;                    \
        _Pragma("unroll")                                                 \
        for (int i = 0; i < 16; i++) cp16(md + lane*16 + i*512, gm + lane*16 + i*512); \
        _Pragma("unroll")                                                 \
        for (int i = 0; i < 16; i++) cp16(pd + lane*16 + i*512, gp + lane*16 + i*512); \
        CP_COMMIT();                                                      \
        CP_WAIT(1);                                                       \
        WSYNC();                                                          \
    } while (0)

    // chunk NCH-1: rows CH-2..0
    {
#pragma unroll 16
        for (int r = CH - 2; r >= 0; r--) BSTEP((NCH - 1) * CH + r, r, mW1, potW1);
        STAGE_BT(NCH - 1);
    }
    for (int c = NCH - 2; c >= 1; c--) {
        const float* mc  = (c & 1) ? mW1 : mW0;
        const float* pcS = (c & 1) ? potW1 : potW0;
#pragma unroll 16
        for (int r = CH - 1; r >= 0; r--) BSTEP(c * CH + r, r, mc, pcS);
        if (c >= 2) {
            STAGE_BT(c);
        } else {
            CP_WAIT(0);
            WSYNC();
        }
    }
    // chunk 0: rows CH-1..1
    {
#pragma unroll 16
        for (int r = CH - 1; r >= 1; r--) BSTEP(r, r, mW0, potW0);
    }
    // last step: t=1 -> tag(0)
    {
        const float target = __shfl_sync(FULL, mcur, tag);
        const float tv = trColS[tag * K + lane];
        const float v = pot0 + tv;
        tag = __ffs(__ballot_sync(FULL, v == target)) - 1;
        ob[0] = (lane == tag) ? 1.0f : 0.0f;
    }
}

extern "C" void kernel_launch(void* const* d_in, const int* in_sizes, int n_in,
                              void* d_out, int out_size)
{
    const float* pot   = (const float*)d_in[0];
    const float* trans = (const float*)d_in[1];
    float* outp        = (float*)d_out;
    cudaFuncSetAttribute(crf_viterbi_kernel,
                         cudaFuncAttributeMaxDynamicSharedMemorySize, SMEM_DYN_BYTES);
    crf_viterbi_kernel<<<B / WPC, WPC * 32, SMEM_DYN_BYTES>>>(pot, trans, outp);
}

// round 16
// speedup vs baseline: 1.6035x; 1.0257x over previous
#include <cuda_runtime.h>
#include <cstdint>

#define B 512
#define T 2048
#define K 32
#define CH 64            // time steps per staged chunk
#define NCH (T / CH)     // 32 chunks
#define WPC 4            // warps (batches) per CTA -> 1 per SMSP, grid=128
#define CHB (CH * K * 4) // 8192
#define FULL 0xffffffffu

#define POT_F (WPC * 2 * CH * K)
#define M_F   (WPC * 2 * CH * K)
#define SMEM_DYN_BYTES ((POT_F + M_F + K * K + WPC * K) * 4)

// m-trace; last 2 chunks per batch never hit gmem
__device__ float g_m[(size_t)B * T * K];

#define ADD2(out, a, b) asm("add.rn.f32x2 %0, %1, %2;" : "=l"(out) : "l"(a), "l"(b))
#define UNPK(lo, hi, v) asm("mov.b64 {%0, %1}, %2;" : "=f"(lo), "=f"(hi) : "l"(v))
#define WSYNC()         __syncwarp()

__device__ __forceinline__ void cp16(uint32_t saddr, const void* gptr) {
    asm volatile("cp.async.cg.shared.global [%0], [%1], 16;" :: "r"(saddr), "l"(gptr));
}
#define CP_COMMIT()  asm volatile("cp.async.commit_group;")
#define CP_WAIT(n)   asm volatile("cp.async.wait_group %0;" :: "n"(n))

__device__ __forceinline__ void bulk_s2g(void* gdst, uint32_t ssrc, uint32_t bytes) {
    asm volatile("cp.async.bulk.global.shared::cta.bulk_group [%0], [%1], %2;"
                 :: "l"(gdst), "r"(ssrc), "r"(bytes) : "memory");
}
#define BULK_COMMIT()    asm volatile("cp.async.bulk.commit_group;")
#define BULK_WAIT_RD(n)  asm volatile("cp.async.bulk.wait_group.read %0;" :: "n"(n))
#define BULK_WAIT(n)     asm volatile("cp.async.bulk.wait_group %0;" :: "n"(n))
#define FENCE_ASYNC()    asm volatile("fence.proxy.async.shared::cta;" ::: "memory")

__global__ void __launch_bounds__(WPC * 32, 1) crf_viterbi_kernel(
    const float* __restrict__ pot,     // [B, T, K]
    const float* __restrict__ trans,   // [K, K]
    float* __restrict__ out)           // [B, T, K] one-hot
{
    extern __shared__ __align__(16) float dyn[];
    float* potBase = dyn;
    float* mBase   = dyn + POT_F;
    float* trColS  = mBase + M_F;              // trColS[j*K+i] = trans[i][j]
    float* stBase  = trColS + K * K;

    const int lane = threadIdx.x & 31;
    const int w    = threadIdx.x >> 5;
    const int b    = blockIdx.x * WPC + w;

    const char* pB = (const char*)(pot + (size_t)b * T * K);
    const char* mB = (const char*)(g_m + (size_t)b * T * K);
    float* ob      = out + (size_t)b * T * K + lane;

    float* potW0 = potBase + (w * 2 + 0) * CH * K;
    float* potW1 = potBase + (w * 2 + 1) * CH * K;
    float* mW0   = mBase + (w * 2 + 0) * CH * K;
    float* mW1   = mBase + (w * 2 + 1) * CH * K;
    float* stW   = stBase + w * K;
    const uint32_t potA0 = (uint32_t)__cvta_generic_to_shared(potW0);
    const uint32_t potA1 = (uint32_t)__cvta_generic_to_shared(potW1);
    const uint32_t mA0   = (uint32_t)__cvta_generic_to_shared(mW0);
    const uint32_t mA1   = (uint32_t)__cvta_generic_to_shared(mW1);

    // packed transition column `lane`: tj2[q] = (trans[2q][lane], trans[2q+1][lane])
    unsigned long long tj2[16];
#pragma unroll
    for (int q = 0; q < 16; q++) {
        float lo = __ldg(trans + (2 * q) * K + lane);
        float hi = __ldg(trans + (2 * q + 1) * K + lane);
        asm("mov.b64 %0, {%1, %2};" : "=l"(tj2[q]) : "f"(lo), "f"(hi));
    }
    if (w == 0) {
#pragma unroll
        for (int i = 0; i < K; i++) trColS[lane * K + i] = trans[i * K + lane];
    }
    __syncthreads();

    // ---- stage forward chunks 0 and 1 ----
#pragma unroll
    for (int i = 0; i < 16; i++)
        cp16(potA0 + lane * 16 + i * 512, pB + lane * 16 + i * 512);
    CP_COMMIT();
#pragma unroll
    for (int i = 0; i < 16; i++)
        cp16(potA1 + lane * 16 + i * 512, pB + CHB + lane * 16 + i * 512);
    CP_COMMIT();
    CP_WAIT(1);
    WSYNC();

    float s = potW0[lane];            // s(0) = pot(0)
    const float pot0 = s;
    float mlast = 0.0f;

// forward step: pcurv is a pre-loaded register (prefetched previous iter).
// STS first (start visibility timer), ladder-tail final combine (exact).
#define FSTEP(pcurv, r, mrow) do {                                        \
        stW[lane] = s;                                                    \
        const ulonglong2* sp = (const ulonglong2*)stW;                    \
        unsigned long long v2[16];                                        \
        _Pragma("unroll")                                                 \
        for (int q = 0; q < 8; q++) {                                     \
            ulonglong2 rr = sp[q];                                        \
            ADD2(v2[2 * q],     rr.x, tj2[2 * q]);                        \
            ADD2(v2[2 * q + 1], rr.y, tj2[2 * q + 1]);                    \
        }                                                                 \
        float m0[16];                                                     \
        _Pragma("unroll")                                                 \
        for (int q = 0; q < 16; q++) {                                    \
            float lo, hi; UNPK(lo, hi, v2[q]);                            \
            m0[q] = fmaxf(lo, hi);                                        \
        }                                                                 \
        float m1[8];                                                      \
        _Pragma("unroll")                                                 \
        for (int q = 0; q < 8; q++) m1[q] = fmaxf(m0[2*q], m0[2*q+1]);    \
        float m2[4];                                                      \
        _Pragma("unroll")                                                 \
        for (int q = 0; q < 4; q++) m2[q] = fmaxf(m1[2*q], m1[2*q+1]);    \
        const float mA_ = fmaxf(m2[0], m2[1]);                            \
        const float mB_ = fmaxf(mA_, m2[2]);                              \
        const float m   = fmaxf(mB_, m2[3]);                              \
        (mrow)[(r) * K + lane] = m;                                       \
        s = m + (pcurv);                                                  \
        mlast = m;                                                        \
    } while (0)

    // ================= forward =================
    // chunk 0 (rows 1..CH-1), peeled
    {
        float pcpre = potW0[1 * K + lane];
#pragma unroll 16
        for (int r = 1; r < CH; r++) {
            const float pcur = pcpre;
            const int rn = (r < CH - 1) ? r + 1 : r;
            pcpre = potW0[rn * K + lane];
            FSTEP(pcur, r, mW0);
        }
        WSYNC();
        FENCE_ASYNC();
        if (lane == 0) {
            bulk_s2g((void*)mB, mA0, CHB);
            BULK_COMMIT();
            BULK_WAIT_RD(1);
        }
        const char* src = pB + 2 * (size_t)CHB;
#pragma unroll
        for (int i = 0; i < 16; i++)
            cp16(potA0 + lane * 16 + i * 512, src + lane * 16 + i * 512);
        CP_COMMIT();
        CP_WAIT(1);
        WSYNC();
    }
    for (int c = 1; c < NCH; c++) {
        const float* pc = (c & 1) ? potW1 : potW0;
        float* mrow     = (c & 1) ? mW1 : mW0;
        float pcpre = pc[lane];
#pragma unroll 16
        for (int r = 0; r < CH; r++) {
            const float pcur = pcpre;
            const int rn = (r < CH - 1) ? r + 1 : r;
            pcpre = pc[rn * K + lane];
            FSTEP(pcur, r, mrow);
        }
        WSYNC();
        if (c <= NCH - 3) {
            FENCE_ASYNC();
            if (lane == 0) {
                bulk_s2g((void*)(mB + (size_t)c * CHB), (c & 1) ? mA1 : mA0, CHB);
                BULK_COMMIT();
                BULK_WAIT_RD(1);
            }
        }
        if (c + 2 < NCH) {
            const uint32_t dst = ((c & 1) == 0) ? potA0 : potA1;
            const char* src = pB + (size_t)(c + 2) * CHB;
#pragma unroll
            for (int i = 0; i < 16; i++)
                cp16(dst + lane * 16 + i * 512, src + lane * 16 + i * 512);
            CP_COMMIT();
            CP_WAIT(1);
            WSYNC();
        } else if (c + 1 < NCH) {
            CP_WAIT(0);
            WSYNC();
        }
    }

    // ---- final tag ----
    float mm = s;
#pragma unroll
    for (int off = 16; off; off >>= 1) mm = fmaxf(mm, __shfl_xor_sync(FULL, mm, off));
    int tag = __ffs(__ballot_sync(FULL, s == mm)) - 1;
    ob[(size_t)(T - 1) * K] = (lane == tag) ? 1.0f : 0.0f;

    if (lane == 0) BULK_WAIT(0);
    WSYNC();

    // ================= backtrack (chunks NCH-1, NCH-2 resident) =================
    float mcur = mlast;

// backtrack step: mprev/pprev come from prefetched registers (mpv, ppv)
#define BSTEP(tp, mpv, ppv) do {                                          \
        const float sprev = (mpv) + (ppv);                                \
        const float target = __shfl_sync(FULL, mcur, tag);                \
        const float tv = trColS[tag * K + lane];                          \
        const unsigned msk = __ballot_sync(FULL, sprev + tv == target);   \
        tag = __ffs(msk) - 1;                                             \
        mcur = (mpv);                                                     \
        ob[(size_t)(tp) * K] = (lane == tag) ? 1.0f : 0.0f;               \
    } while (0)

#define STAGE_BT(c) do {                                                  \
        const uint32_t md = (((c) & 1) == 0) ? mA0 : mA1;                 \
        const uint32_t pd = (((c) & 1) == 0) ? potA0 : potA1;             \
        const char* gm = mB + (size_t)((c) - 2) * CHB;                    \
        const char* gp = pB + (size_t)((c) - 2) * CHB;                    \
        _Pragma("unroll")                                                 \
        for (int i = 0; i < 16; i++) cp16(md + lane*16 + i*512, gm + lane*16 + i*512); \
        _Pragma("unroll")                                                 \
        for (int i = 0; i < 16; i++) cp16(pd + lane*16 + i*512, gp + lane*16 + i*512); \
        CP_COMMIT();                                                      \
        CP_WAIT(1);                                                       \
        WSYNC();                                                          \
    } while (0)

    // chunk NCH-1: rows CH-2..0
    {
        const float* mc  = mW1;   // (NCH-1)&1 == 1
        const float* pcS = potW1;
        float mpre = mc[(CH - 2) * K + lane];
        float ppre = pcS[(CH - 2) * K + lane];
#pragma unroll 16
        for (int r = CH - 2; r >= 0; r--) {
            const float mpv = mpre, ppv = ppre;
            const int rn = (r > 0) ? r - 1 : 0;
            mpre = mc[rn * K + lane];
            ppre = pcS[rn * K + lane];
            BSTEP((NCH - 1) * CH + r, mpv, ppv);
        }
        STAGE_BT(NCH - 1);
    }
    for (int c = NCH - 2; c >= 1; c--) {
        const float* mc  = (c & 1) ? mW1 : mW0;
        const float* pcS = (c & 1) ? potW1 : potW0;
        float mpre = mc[(CH - 1) * K + lane];
        float ppre = pcS[(CH - 1) * K + lane];
#pragma unroll 16
        for (int r = CH - 1; r >= 0; r--) {
            const float mpv = mpre, ppv = ppre;
            const int rn = (r > 0) ? r - 1 : 0;
            mpre = mc[rn * K + lane];
            ppre = pcS[rn * K + lane];
            BSTEP(c * CH + r, mpv, ppv);
        }
        if (c >= 2) {
            STAGE_BT(c);
        } else {
            CP_WAIT(0);
            WSYNC();
        }
    }
    // chunk 0: rows CH-1..1
    {
        float mpre = mW0[(CH - 1) * K + lane];
        float ppre = potW0[(CH - 1) * K + lane];
#pragma unroll 16
        for (int r = CH - 1; r >= 1; r--) {
            const float mpv = mpre, ppv = ppre;
            const int rn = (r > 1) ? r - 1 : 1;
            mpre = mW0[rn * K + lane];
            ppre = potW0[rn * K + lane];
            BSTEP(r, mpv, ppv);
        }
    }
    // last step: t=1 -> tag(0)
    {
        const float target = __shfl_sync(FULL, mcur, tag);
        const float tv = trColS[tag * K + lane];
        const float v = pot0 + tv;
        tag = __ffs(__ballot_sync(FULL, v == target)) - 1;
        ob[0] = (lane == tag) ? 1.0f : 0.0f;
    }
}

extern "C" void kernel_launch(void* const* d_in, const int* in_sizes, int n_in,
                              void* d_out, int out_size)
{
    const float* pot   = (const float*)d_in[0];
    const float* trans = (const float*)d_in[1];
    float* outp        = (float*)d_out;
    cudaFuncSetAttribute(crf_viterbi_kernel,
                         cudaFuncAttributeMaxDynamicSharedMemorySize, SMEM_DYN_BYTES);
    crf_viterbi_kernel<<<B / WPC, WPC * 32, SMEM_DYN_BYTES>>>(pot, trans, outp);
}